// round 2
// baseline (speedup 1.0000x reference)
#include <cuda_runtime.h>

#define CIN   16
#define COUT  16
#define HH    1024
#define WW    1024
#define BB    8
#define TH    16
#define TW    32
#define SIN_H 18
#define SIN_W 35          // padded from 34; 35 % 32 = 3 -> conflict-free rows
#define SMEM_IN_FLOATS (CIN * SIN_H * SIN_W)                 // 10080
#define SMEM_W_ULL     (CIN * 9 * COUT)                      // 2304 float2 pairs
#define SMEM_BYTES     (SMEM_IN_FLOATS * 4 + SMEM_W_ULL * 8) // 58752

__device__ __forceinline__ unsigned long long pack2(float lo, float hi) {
    unsigned long long r;
    asm("mov.b64 %0, {%1, %2};" : "=l"(r) : "f"(lo), "f"(hi));
    return r;
}

__device__ __forceinline__ unsigned long long ffma2(unsigned long long a,
                                                    unsigned long long b,
                                                    unsigned long long c) {
    unsigned long long d;
    asm("fma.rn.f32x2 %0, %1, %2, %3;" : "=l"(d) : "l"(a), "l"(b), "l"(c));
    return d;
}

__device__ __forceinline__ void unpack2(unsigned long long v, float& lo, float& hi) {
    asm("mov.b64 {%0, %1}, %2;" : "=f"(lo), "=f"(hi) : "l"(v));
}

__global__ __launch_bounds__(128)
void conv3x3_kernel(const float* __restrict__ x,
                    const float* __restrict__ wg,
                    float* __restrict__ out) {
    extern __shared__ float smem[];
    float* sIn = smem;                                            // [CIN][SIN_H][SIN_W]
    unsigned long long* sW =
        reinterpret_cast<unsigned long long*>(smem + SMEM_IN_FLOATS); // [(cin*9+tap)*16+co]

    const int tid = threadIdx.x;
    const int bx = blockIdx.x;   // W / TW = 32
    const int by = blockIdx.y;   // H / TH = 64
    const int b  = blockIdx.z;   // B = 8

    // ---- load weights, duplicated into both f32x2 lanes ----
    // sW[(cin*9+tap)*16 + co] = W[co][cin][tap]  (OIHW)
    for (int i = tid; i < CIN * 9 * COUT; i += 128) {
        int co   = i & 15;
        int rest = i >> 4;
        int tap  = rest % 9;
        int cin  = rest / 9;
        float w = wg[(co * CIN + cin) * 9 + tap];
        sW[i] = pack2(w, w);
    }

    // ---- load input tile with halo (zero padded at image borders) ----
    const int x0 = bx * TW - 1;
    const int y0 = by * TH - 1;
    const float* xb = x + (size_t)b * CIN * HH * WW;
    const int lane = tid & 31;
    const int wrp  = tid >> 5;

    for (int cin = 0; cin < CIN; cin++) {
        const float* src = xb + (size_t)cin * HH * WW;
        float* dst = sIn + cin * SIN_H * SIN_W;
        for (int iy = wrp; iy < SIN_H; iy += 4) {
            int gy = y0 + iy;
            bool yok = (unsigned)gy < (unsigned)HH;
            const float* srow = src + (size_t)gy * WW;
            int gx1 = x0 + lane;
            float v1 = (yok && (unsigned)gx1 < (unsigned)WW) ? srow[gx1] : 0.0f;
            dst[iy * SIN_W + lane] = v1;
            if (lane < 2) {
                int gx2 = x0 + lane + 32;
                float v2 = (yok && (unsigned)gx2 < (unsigned)WW) ? srow[gx2] : 0.0f;
                dst[iy * SIN_W + lane + 32] = v2;
            }
        }
    }
    __syncthreads();

    // ---- compute: 4 pixels (x-adjacent) x 16 cout per thread via f32x2 ----
    const int tx = (tid & 7) * 4;   // 0..28
    const int ty = tid >> 3;        // 0..15

    unsigned long long accA[COUT];  // pixels 0,1
    unsigned long long accB[COUT];  // pixels 2,3
#pragma unroll
    for (int co = 0; co < COUT; co++) { accA[co] = 0ULL; accB[co] = 0ULL; }

#pragma unroll 1
    for (int cin = 0; cin < CIN; cin++) {
        const float* base = sIn + cin * SIN_H * SIN_W;
        const unsigned long long* wbase = sW + cin * 9 * COUT;
#pragma unroll
        for (int dy = 0; dy < 3; dy++) {
            const float* r = base + (ty + dy) * SIN_W + tx;
            float v0 = r[0], v1 = r[1], v2 = r[2], v3 = r[3], v4 = r[4], v5 = r[5];
            unsigned long long pr0 = pack2(v0, v1);
            unsigned long long pr1 = pack2(v1, v2);
            unsigned long long pr2 = pack2(v2, v3);
            unsigned long long pr3 = pack2(v3, v4);
            unsigned long long pr4 = pack2(v4, v5);
            const unsigned long long* wrow = wbase + dy * 3 * COUT;
            // dx = 0: pairs (pr0, pr2); dx = 1: (pr1, pr3); dx = 2: (pr2, pr4)
#pragma unroll
            for (int co = 0; co < COUT; co++) {
                unsigned long long w2 = wrow[co];
                accA[co] = ffma2(pr0, w2, accA[co]);
                accB[co] = ffma2(pr2, w2, accB[co]);
            }
#pragma unroll
            for (int co = 0; co < COUT; co++) {
                unsigned long long w2 = wrow[COUT + co];
                accA[co] = ffma2(pr1, w2, accA[co]);
                accB[co] = ffma2(pr3, w2, accB[co]);
            }
#pragma unroll
            for (int co = 0; co < COUT; co++) {
                unsigned long long w2 = wrow[2 * COUT + co];
                accA[co] = ffma2(pr2, w2, accA[co]);
                accB[co] = ffma2(pr4, w2, accB[co]);
            }
        }
    }

    // ---- store: float4 per cout ----
    const int gx = bx * TW + tx;
    const int gy = by * TH + ty;
    float* ob = out + (size_t)b * COUT * HH * WW;
#pragma unroll
    for (int co = 0; co < COUT; co++) {
        float a0, a1, b0, b1;
        unpack2(accA[co], a0, a1);
        unpack2(accB[co], b0, b1);
        float4 res = make_float4(a0, a1, b0, b1);
        *reinterpret_cast<float4*>(&ob[((size_t)co * HH + gy) * WW + gx]) = res;
    }
}

extern "C" void kernel_launch(void* const* d_in, const int* in_sizes, int n_in,
                              void* d_out, int out_size) {
    const float* x = (const float*)d_in[0];
    const float* w = (const float*)d_in[1];
    // Defensive: weights have 2304 elements, input 134217728.
    if (n_in >= 2 && in_sizes[0] == COUT * CIN * 9) {
        const float* t = x; x = w; w = t;
    }
    float* out = (float*)d_out;

    cudaFuncSetAttribute(conv3x3_kernel,
                         cudaFuncAttributeMaxDynamicSharedMemorySize, SMEM_BYTES);
    dim3 grid(WW / TW, HH / TH, BB);
    conv3x3_kernel<<<grid, 128, SMEM_BYTES>>>(x, w, out);
}

// round 4
// speedup vs baseline: 1.4296x; 1.4296x over previous
#include <cuda_runtime.h>
#include <cstdint>

#define TY   16
#define TWX  32
#define SYY  18
#define SXX  34
#define PLW    (SYY * SXX * 8)            // words per kstep plane = 4896
#define SMB_W  (2 * PLW)                  // B base (words) = 9792
#define SMEM_WORDS (SMB_W + 9 * 2 * 16 * 8)   // + 2304 = 12096
#define SMEM_BYTES (SMEM_WORDS * 4)           // 48384

static __device__ __forceinline__ uint32_t cvt_tf32(float f) {
    uint32_t r;
    asm("cvt.rna.tf32.f32 %0, %1;" : "=r"(r) : "f"(f));
    return r;
}

static __device__ __forceinline__ void mma_tf32(float& c0, float& c1, float& c2, float& c3,
                                                uint32_t a0, uint32_t a1, uint32_t a2, uint32_t a3,
                                                uint32_t b0, uint32_t b1) {
    asm volatile(
        "mma.sync.aligned.m16n8k8.row.col.f32.tf32.tf32.f32 "
        "{%0,%1,%2,%3}, {%4,%5,%6,%7}, {%8,%9}, {%0,%1,%2,%3};"
        : "+f"(c0), "+f"(c1), "+f"(c2), "+f"(c3)
        : "r"(a0), "r"(a1), "r"(a2), "r"(a3), "r"(b0), "r"(b1));
}

__global__ __launch_bounds__(256, 2)
void conv_mma_kernel(const float* __restrict__ x,
                     const float* __restrict__ wg,
                     float* __restrict__ out)
{
    extern __shared__ uint32_t sm[];
    const int tid = threadIdx.x, wid = tid >> 5, lane = tid & 31;
    const int g = lane >> 2, t = lane & 3;             // quad row / thread-in-quad
    const int x0 = blockIdx.x * TWX;
    const int y0 = blockIdx.y * TY;
    const int b  = blockIdx.z;

    // ---- weights -> smem B: sB[(tap*2+s)*16 + n][ t*2 + half ], pair (k=t, k=t+4) adjacent ----
    for (int i = tid; i < 16 * 16 * 9; i += 256) {
        const int dxy = i % 9;            // dy*3+dx
        const int cin = (i / 9) & 15;
        const int co  = i / 144;
        const int s = cin >> 3, cc = cin & 7;
        sm[SMB_W + ((dxy * 2 + s) * 16 + co) * 8 + (cc & 3) * 2 + (cc >> 2)] = cvt_tf32(wg[i]);
    }

    // ---- input tile -> smem A: sA[s][yy][xx][ w = cc ^ ((xx>>2)&7) ]  (tf32) ----
    const float* xbp = x + (size_t)b * 16 * 1024 * 1024;
    for (int p = wid; p < SYY * 16; p += 8) {
        const int yy = p >> 4, cin = p & 15;
        const int gy = y0 - 1 + yy;
        const bool yok = (unsigned)gy < 1024u;
        const float* row = xbp + ((size_t)cin * 1024 + (yok ? gy : 0)) * 1024;
        const int s = cin >> 3, cc = cin & 7;
        const uint32_t pbase = s * PLW + yy * (SXX * 8);
        {
            const int xx = lane;
            const int gx = x0 - 1 + xx;
            const float v = (yok && (unsigned)gx < 1024u) ? row[gx] : 0.0f;
            sm[pbase + xx * 8 + (cc ^ ((xx >> 2) & 7))] = cvt_tf32(v);
        }
        if (lane < 2) {
            const int xx = 32 + lane;
            const int gx = x0 - 1 + xx;
            const float v = (yok && (unsigned)gx < 1024u) ? row[gx] : 0.0f;
            sm[pbase + xx * 8 + (cc ^ ((xx >> 2) & 7))] = cvt_tf32(v);
        }
    }
    __syncthreads();

    // ---- mainloop: 9 taps x 2 ksteps x 4 m-tiles x 2 n-tiles ----
    float C[4][2][4];
#pragma unroll
    for (int mt = 0; mt < 4; mt++)
#pragma unroll
        for (int nt = 0; nt < 2; nt++)
#pragma unroll
            for (int r = 0; r < 4; r++) C[mt][nt][r] = 0.0f;

    const int yw = 2 * wid;          // warp's two local output rows: yw, yw+1

#pragma unroll 1
    for (int tap = 0; tap < 9; tap++) {
        const int dy = tap / 3, dx = tap % 3;
#pragma unroll
        for (int s = 0; s < 2; s++) {
            const uint32_t bb = SMB_W + ((tap * 2 + s) * 16 + g) * 8 + t * 2;
            const uint2 bn0 = *(const uint2*)&sm[bb];        // n = g
            const uint2 bn1 = *(const uint2*)&sm[bb + 64];   // n = 8 + g
            const uint32_t plane = s * PLW;
#pragma unroll
            for (int mt = 0; mt < 4; mt++) {
                const int yy  = yw + (mt >> 1) + dy;
                const int xx0 = (mt & 1) * 16 + g + dx;      // m rows 0..7
                const int xx1 = xx0 + 8;                     // m rows 8..15
                const uint32_t r0 = plane + yy * (SXX * 8) + xx0 * 8;
                const uint32_t r1 = r0 + 64;                 // xx1 = xx0+8 -> +64 words
                const int w0 = t ^ ((xx0 >> 2) & 7);
                const int w1 = t ^ ((xx1 >> 2) & 7);
                const uint32_t a0 = sm[r0 + w0];
                const uint32_t a1 = sm[r1 + w1];
                const uint32_t a2 = sm[r0 + (w0 ^ 4)];       // k = t+4
                const uint32_t a3 = sm[r1 + (w1 ^ 4)];
                mma_tf32(C[mt][0][0], C[mt][0][1], C[mt][0][2], C[mt][0][3],
                         a0, a1, a2, a3, bn0.x, bn0.y);
                mma_tf32(C[mt][1][0], C[mt][1][1], C[mt][1][2], C[mt][1][3],
                         a0, a1, a2, a3, bn1.x, bn1.y);
            }
        }
    }

    // ---- epilogue: c0,c1 -> (x, co), (x, co+1); c2,c3 -> (x+8, ...) ----
    float* ob = out + (size_t)b * 16 * 1024 * 1024;
#pragma unroll
    for (int mt = 0; mt < 4; mt++) {
        const int y  = y0 + yw + (mt >> 1);
        const int xg = x0 + (mt & 1) * 16 + g;
#pragma unroll
        for (int nt = 0; nt < 2; nt++) {
            const int co = nt * 8 + 2 * t;
            float* p0 = ob + ((size_t)co * 1024 + y) * 1024;
            float* p1 = p0 + 1024 * 1024;                    // co + 1
            p0[xg]     = C[mt][nt][0];
            p1[xg]     = C[mt][nt][1];
            p0[xg + 8] = C[mt][nt][2];
            p1[xg + 8] = C[mt][nt][3];
        }
    }
}

extern "C" void kernel_launch(void* const* d_in, const int* in_sizes, int n_in,
                              void* d_out, int out_size) {
    const float* x = (const float*)d_in[0];
    const float* w = (const float*)d_in[1];
    if (n_in >= 2 && in_sizes[0] == 16 * 16 * 9) {     // defensive order check
        const float* tp = x; x = w; w = tp;
    }
    float* out = (float*)d_out;

    cudaFuncSetAttribute(conv_mma_kernel,
                         cudaFuncAttributeMaxDynamicSharedMemorySize, SMEM_BYTES);
    dim3 grid(1024 / TWX, 1024 / TY, 8);
    conv_mma_kernel<<<grid, 256, SMEM_BYTES>>>(x, w, out);
}

// round 5
// speedup vs baseline: 2.4955x; 1.7456x over previous
#include <cuda_runtime.h>
#include <cstdint>

#define TWX  32
#define TY   8
#define SYY  10                 // TY + 2 halo rows
#define SXX  34                 // TWX + 2 halo cols
#define RW   34                 // row stride (words)
#define PL   344                // plane stride (words); 344 % 32 == 24 -> conflict-free
#define SMA_W  0
#define SMB_W  (16 * PL)        // 5504 words
#define SMEM_WORDS (SMB_W + 9 * 2 * 16 * 8)   // + 2304 = 7808
#define SMEM_BYTES (SMEM_WORDS * 4)           // 31232

static __device__ __forceinline__ uint32_t cvt_tf32(float f) {
    uint32_t r;
    asm("cvt.rna.tf32.f32 %0, %1;" : "=r"(r) : "f"(f));
    return r;
}

static __device__ __forceinline__ void mma_tf32(float& c0, float& c1, float& c2, float& c3,
                                                uint32_t a0, uint32_t a1, uint32_t a2, uint32_t a3,
                                                uint32_t b0, uint32_t b1) {
    asm volatile(
        "mma.sync.aligned.m16n8k8.row.col.f32.tf32.tf32.f32 "
        "{%0,%1,%2,%3}, {%4,%5,%6,%7}, {%8,%9}, {%0,%1,%2,%3};"
        : "+f"(c0), "+f"(c1), "+f"(c2), "+f"(c3)
        : "r"(a0), "r"(a1), "r"(a2), "r"(a3), "r"(b0), "r"(b1));
}

__global__ __launch_bounds__(256, 4)
void conv_mma_kernel(const float* __restrict__ x,
                     const float* __restrict__ wg,
                     float* __restrict__ out)
{
    extern __shared__ uint32_t sm[];
    const int tid = threadIdx.x, wid = tid >> 5, lane = tid & 31;
    const int g = lane >> 2, t = lane & 3;            // quad row / thread-in-quad
    const int x0 = blockIdx.x * TWX;
    const int y0 = blockIdx.y * TY;
    const int b  = blockIdx.z;

    // ---- weights -> smem B: word = ((tap*2+s)*16 + co)*8 + (cc&3)*2 + (cc>>2) ----
    // wg is OIHW: i = ((co*16 + cin)*3 + dy)*3 + dx
    for (int i = tid; i < 16 * 16 * 9; i += 256) {
        const int dxy = i % 9;                        // dy*3+dx = tap
        const int cin = (i / 9) & 15;
        const int co  = i / 144;
        const int s = cin >> 3, cc = cin & 7;
        sm[SMB_W + ((dxy * 2 + s) * 16 + co) * 8 + (cc & 3) * 2 + (cc >> 2)] = cvt_tf32(wg[i]);
    }

    // ---- input tile -> smem A: sA[cin][yy][xx] (tf32), raw layout ----
    const float* xbp = x + (size_t)b * 16 * 1024 * 1024;
    for (int p = wid; p < 16 * SYY; p += 8) {         // (cin, yy) pairs
        const int cin = p & 15, yy = p >> 4;
        const int gy = y0 - 1 + yy;
        const bool yok = (unsigned)gy < 1024u;
        const float* row = xbp + ((size_t)cin * 1024 + (yok ? gy : 0)) * 1024;
        const uint32_t base = cin * PL + yy * RW;
        {
            const int xx = lane;                      // 0..31
            const int gx = x0 - 1 + xx;
            const float v = (yok && (unsigned)gx < 1024u) ? row[gx] : 0.0f;
            sm[base + xx] = cvt_tf32(v);
        }
        if (lane < 2) {
            const int xx = 32 + lane;                 // 32, 33
            const int gx = x0 - 1 + xx;
            const float v = (yok && (unsigned)gx < 1024u) ? row[gx] : 0.0f;
            sm[base + xx] = cvt_tf32(v);
        }
    }
    __syncthreads();

    // ---- mainloop: warp handles output row yw = wid, 32 x-pixels (2 m-tiles) ----
    float C[2][2][4];
#pragma unroll
    for (int mt = 0; mt < 2; mt++)
#pragma unroll
        for (int nt = 0; nt < 2; nt++)
#pragma unroll
            for (int r = 0; r < 4; r++) C[mt][nt][r] = 0.0f;

    const int yw = wid;
    const uint32_t* pa = sm + t * PL + yw * RW + g;          // lane A base
    const uint2*    pb = (const uint2*)(sm + SMB_W) + g * 4 + t;  // lane B base

#pragma unroll
    for (int tap = 0; tap < 9; tap++) {
        const int dy = tap / 3, dx = tap % 3;
#pragma unroll
        for (int s = 0; s < 2; s++) {
            const uint2 bn0 = pb[(tap * 2 + s) * 64];        // n = g
            const uint2 bn1 = pb[(tap * 2 + s) * 64 + 32];   // n = g + 8
            const int o = s * (8 * PL) + dy * RW + dx;       // compile-time constant
#pragma unroll
            for (int mt = 0; mt < 2; mt++) {
                const int om = o + mt * 16;
                const uint32_t a0 = pa[om];                  // m = g,    k = t
                const uint32_t a1 = pa[om + 8];              // m = g+8,  k = t
                const uint32_t a2 = pa[om + 4 * PL];         // m = g,    k = t+4
                const uint32_t a3 = pa[om + 4 * PL + 8];     // m = g+8,  k = t+4
                mma_tf32(C[mt][0][0], C[mt][0][1], C[mt][0][2], C[mt][0][3],
                         a0, a1, a2, a3, bn0.x, bn0.y);
                mma_tf32(C[mt][1][0], C[mt][1][1], C[mt][1][2], C[mt][1][3],
                         a0, a1, a2, a3, bn1.x, bn1.y);
            }
        }
    }

    // ---- epilogue: c0,c1 -> (x, co), (x, co+1); c2,c3 -> (x+8, ...) ----
    float* ob = out + (size_t)b * 16 * 1024 * 1024;
    const int y = y0 + yw;
#pragma unroll
    for (int mt = 0; mt < 2; mt++) {
        const int xg = x0 + mt * 16 + g;
#pragma unroll
        for (int nt = 0; nt < 2; nt++) {
            const int co = nt * 8 + 2 * t;
            float* p0 = ob + ((size_t)co * 1024 + y) * 1024;
            float* p1 = p0 + 1024 * 1024;                    // co + 1
            p0[xg]     = C[mt][nt][0];
            p1[xg]     = C[mt][nt][1];
            p0[xg + 8] = C[mt][nt][2];
            p1[xg + 8] = C[mt][nt][3];
        }
    }
}

extern "C" void kernel_launch(void* const* d_in, const int* in_sizes, int n_in,
                              void* d_out, int out_size) {
    const float* x = (const float*)d_in[0];
    const float* w = (const float*)d_in[1];
    if (n_in >= 2 && in_sizes[0] == 16 * 16 * 9) {     // defensive order check
        const float* tp = x; x = w; w = tp;
    }
    float* out = (float*)d_out;

    cudaFuncSetAttribute(conv_mma_kernel,
                         cudaFuncAttributeMaxDynamicSharedMemorySize, SMEM_BYTES);
    dim3 grid(1024 / TWX, 1024 / TY, 8);
    conv_mma_kernel<<<grid, 256, SMEM_BYTES>>>(x, w, out);
}

// round 6
// speedup vs baseline: 3.2832x; 1.3157x over previous
#include <cuda_runtime.h>
#include <cstdint>

#define TWX  32
#define TY   16
#define SYY  18                 // TY + 2 halo rows
#define RW   34                 // row stride (words)
#define PL   616                // plane stride; 616 % 32 == 8 -> t*PL banks {0,8,16,24}
#define SMB_W  (16 * PL)        // 9856 words
#define SMEM_WORDS (SMB_W + 9 * 2 * 16 * 8)   // + 2304 = 12160
#define SMEM_BYTES (SMEM_WORDS * 4)           // 48640

static __device__ __forceinline__ uint32_t cvt_tf32(float f) {
    uint32_t r;
    asm("cvt.rna.tf32.f32 %0, %1;" : "=r"(r) : "f"(f));
    return r;
}

static __device__ __forceinline__ void mma_tf32(float* c,
                                                uint32_t a0, uint32_t a1, uint32_t a2, uint32_t a3,
                                                uint32_t b0, uint32_t b1) {
    asm volatile(
        "mma.sync.aligned.m16n8k8.row.col.f32.tf32.tf32.f32 "
        "{%0,%1,%2,%3}, {%4,%5,%6,%7}, {%8,%9}, {%0,%1,%2,%3};"
        : "+f"(c[0]), "+f"(c[1]), "+f"(c[2]), "+f"(c[3])
        : "r"(a0), "r"(a1), "r"(a2), "r"(a3), "r"(b0), "r"(b1));
}

__global__ __launch_bounds__(256, 3)
void conv_mma_kernel(const float* __restrict__ x,
                     const float* __restrict__ wg,
                     float* __restrict__ out)
{
    extern __shared__ uint32_t sm[];
    const int tid = threadIdx.x, wid = tid >> 5, lane = tid & 31;
    const int g = lane >> 2, t = lane & 3;            // quad row / thread-in-quad
    const int x0 = blockIdx.x * TWX;
    const int y0 = blockIdx.y * TY;
    const int b  = blockIdx.z;

    // ---- weights -> smem B (no div/mod): thread = (co, cin), loop over taps ----
    // layout word: ((tap*2+s)*16 + co)*8 + (cc&3)*2 + (cc>>2)
    {
        const int co = tid >> 4, cin = tid & 15;
        const int s = cin >> 3, cc = cin & 7;
        const int wword = (cc & 3) * 2 + (cc >> 2);
        const float* wp = wg + (co * 16 + cin) * 9;
        uint32_t sa = SMB_W + (s * 16 + co) * 8 + wword;
#pragma unroll
        for (int tap = 0; tap < 9; tap++)
            sm[sa + tap * 256] = cvt_tf32(wp[tap]);   // tap*2*16*8 = 256 words
    }

    // ---- input tile -> smem A: sA[cin][yy][xx], warp owns 2 cin planes ----
    const float* xbp = x + (size_t)b * 16 * 1024 * 1024;
    const int gx_m = x0 - 1 + lane;                    // main column, per-lane const
    const bool xok_m = (unsigned)gx_m < 1024u;         // only lane0 @ bx=0 fails
    const int gx_e = x0 + 31 + lane;                   // extra cols (lanes 0,1)
    const bool xok_e = (lane < 2) && ((unsigned)gx_e < 1024u);
#pragma unroll
    for (int cc2 = 0; cc2 < 2; cc2++) {
        const int cin = wid + cc2 * 8;
        const float* row = xbp + ((size_t)cin * 1024 + (y0 - 1)) * 1024;
        uint32_t sa = cin * PL;
#pragma unroll 1
        for (int yy = 0; yy < SYY; yy++) {
            const int gy = y0 - 1 + yy;
            const bool yok = (unsigned)gy < 1024u;
            float v = 0.0f, ve = 0.0f;
            if (yok && xok_m) v  = row[gx_m];
            if (yok && xok_e) ve = row[gx_e];
            sm[sa + lane] = cvt_tf32(v);
            if (lane < 2) sm[sa + 32 + lane] = cvt_tf32(ve);
            row += 1024;
            sa  += RW;
        }
    }
    __syncthreads();

    // ---- mainloop: warp owns output rows yw, yw+1; loop over input rows li ----
    float C[2][2][2][4];                               // [r][xh][nt][reg]
#pragma unroll
    for (int r = 0; r < 2; r++)
#pragma unroll
        for (int xh = 0; xh < 2; xh++)
#pragma unroll
            for (int nt = 0; nt < 2; nt++)
#pragma unroll
                for (int q = 0; q < 4; q++) C[r][xh][nt][q] = 0.0f;

    const int yw = 2 * wid;
    const uint32_t* pa = sm + t * PL + yw * RW + g;
    const uint2*    pb = (const uint2*)(sm + SMB_W) + g * 4 + t;

#pragma unroll
    for (int s = 0; s < 2; s++) {
#pragma unroll
        for (int li = 0; li < 4; li++) {               // input row yw + li
            uint32_t av[2][3][2][2];                   // [xh][dx][kh][mh]
#pragma unroll
            for (int xh = 0; xh < 2; xh++)
#pragma unroll
                for (int dx = 0; dx < 3; dx++) {
                    const int o = s * (8 * PL) + li * RW + xh * 16 + dx;
                    av[xh][dx][0][0] = pa[o];
                    av[xh][dx][0][1] = pa[o + 8];
                    av[xh][dx][1][0] = pa[o + 4 * PL];
                    av[xh][dx][1][1] = pa[o + 4 * PL + 8];
                }
#pragma unroll
            for (int r = 0; r < 2; r++) {
                const int dy = li - r;
                if (dy >= 0 && dy <= 2) {
#pragma unroll
                    for (int dx = 0; dx < 3; dx++) {
                        const int tap = dy * 3 + dx;
                        const uint2 b0 = pb[(tap * 2 + s) * 64];
                        const uint2 b1 = pb[(tap * 2 + s) * 64 + 32];
#pragma unroll
                        for (int xh = 0; xh < 2; xh++) {
                            mma_tf32(C[r][xh][0],
                                     av[xh][dx][0][0], av[xh][dx][0][1],
                                     av[xh][dx][1][0], av[xh][dx][1][1],
                                     b0.x, b0.y);
                            mma_tf32(C[r][xh][1],
                                     av[xh][dx][0][0], av[xh][dx][0][1],
                                     av[xh][dx][1][0], av[xh][dx][1][1],
                                     b1.x, b1.y);
                        }
                    }
                }
            }
        }
    }

    // ---- epilogue ----
    float* ob = out + (size_t)b * 16 * 1024 * 1024;
#pragma unroll
    for (int r = 0; r < 2; r++) {
        const int y = y0 + yw + r;
#pragma unroll
        for (int xh = 0; xh < 2; xh++) {
            const int xg = x0 + xh * 16 + g;
#pragma unroll
            for (int nt = 0; nt < 2; nt++) {
                const int co = nt * 8 + 2 * t;
                float* p0 = ob + ((size_t)co * 1024 + y) * 1024;
                float* p1 = p0 + 1024 * 1024;          // co + 1
                p0[xg]     = C[r][xh][nt][0];
                p1[xg]     = C[r][xh][nt][1];
                p0[xg + 8] = C[r][xh][nt][2];
                p1[xg + 8] = C[r][xh][nt][3];
            }
        }
    }
}

extern "C" void kernel_launch(void* const* d_in, const int* in_sizes, int n_in,
                              void* d_out, int out_size) {
    const float* x = (const float*)d_in[0];
    const float* w = (const float*)d_in[1];
    if (n_in >= 2 && in_sizes[0] == 16 * 16 * 9) {     // defensive order check
        const float* tp = x; x = w; w = tp;
    }
    float* out = (float*)d_out;

    cudaFuncSetAttribute(conv_mma_kernel,
                         cudaFuncAttributeMaxDynamicSharedMemorySize, SMEM_BYTES);
    dim3 grid(1024 / TWX, 1024 / TY, 8);
    conv_mma_kernel<<<grid, 256, SMEM_BYTES>>>(x, w, out);
}

// round 7
// speedup vs baseline: 9.0765x; 2.7645x over previous
#include <cuda_runtime.h>
#include <cstdint>

#define TWX  32
#define TY   16
#define SYY  18                  // TY + 2 halo rows
#define RW   34                  // row stride in pixels
#define PL   616                 // plane stride (words); 616 % 32 == 8 -> banks {0,8,16,24}+g
#define SMB_W (8 * PL)           // 4928 words
#define B_WORDS (9 * 128)        // 1152
#define SMEM_BYTES ((SMB_W + B_WORDS) * 4)   // 24320

static __device__ __forceinline__ uint32_t pack_h2(float lo, float hi) {
    uint32_t r;
    asm("cvt.rn.f16x2.f32 %0, %1, %2;" : "=r"(r) : "f"(hi), "f"(lo));  // 2nd src -> low half
    return r;
}

static __device__ __forceinline__ void mma_f16(float* c,
                                               uint32_t a0, uint32_t a1, uint32_t a2, uint32_t a3,
                                               uint32_t b0, uint32_t b1) {
    asm volatile(
        "mma.sync.aligned.m16n8k16.row.col.f32.f16.f16.f32 "
        "{%0,%1,%2,%3}, {%4,%5,%6,%7}, {%8,%9}, {%0,%1,%2,%3};"
        : "+f"(c[0]), "+f"(c[1]), "+f"(c[2]), "+f"(c[3])
        : "r"(a0), "r"(a1), "r"(a2), "r"(a3), "r"(b0), "r"(b1));
}

__global__ __launch_bounds__(512, 3)
void conv_mma_kernel(const float* __restrict__ x,
                     const float* __restrict__ wg,
                     float* __restrict__ out)
{
    extern __shared__ uint32_t sm[];
    const int tid = threadIdx.x, wid = tid >> 5, lane = tid & 31;
    const int g = lane >> 2, t = lane & 3;
    const int x0 = blockIdx.x * TWX;
    const int y0 = blockIdx.y * TY;
    const int b  = blockIdx.z;

    // ---- weights -> smem B (half2 pairs): word = tap*128 + co*8 + 2*(p&3) + (p>>2) ----
    if (tid < 128) {
        const int co = tid >> 3, p = tid & 7;
        const float* w0 = wg + (co * 16 + 2 * p) * 9;        // cin = 2p
        const float* w1 = w0 + 9;                            // cin = 2p+1
        const uint32_t sa = SMB_W + co * 8 + 2 * (p & 3) + (p >> 2);
#pragma unroll
        for (int tap = 0; tap < 9; tap++)
            sm[sa + tap * 128] = pack_h2(w0[tap], w1[tap]);  // low = cin 2p (k even)
    }

    // ---- input tile -> smem A: 8 cin-pair planes of packed half2 ----
    // plane p holds half2(cin 2p, cin 2p+1); addr = p*PL + yy*RW + xx
    {
        const int p = wid >> 1;                              // warp pair-plane
        const int ys = wid & 1;                              // rows ys, ys+2, ... (9 rows)
        const float* r0 = x + ((size_t)(b * 16 + 2 * p) * 1024 + (y0 - 1 + ys)) * 1024;
        const float* r1 = r0 + 1024 * 1024;                  // cin 2p+1
        const int gx_m = x0 - 1 + lane;
        const bool xok_m = (unsigned)gx_m < 1024u;
        const int gx_e = x0 + 31 + lane;
        const bool xok_e = (lane < 2) && ((unsigned)gx_e < 1024u);
        uint32_t sa = p * PL + ys * RW;
#pragma unroll
        for (int k = 0; k < 9; k++) {
            const int gy = y0 - 1 + ys + 2 * k;
            const bool yok = (unsigned)gy < 1024u;
            float v0 = 0.f, v1 = 0.f, e0 = 0.f, e1 = 0.f;
            if (yok && xok_m) { v0 = r0[gx_m]; v1 = r1[gx_m]; }
            if (yok && xok_e) { e0 = r0[gx_e]; e1 = r1[gx_e]; }
            sm[sa + lane] = pack_h2(v0, v1);
            if (lane < 2) sm[sa + 32 + lane] = pack_h2(e0, e1);
            r0 += 2048; r1 += 2048;
            sa += 2 * RW;
        }
    }
    __syncthreads();

    // ---- mainloop: warp owns output row yw = wid; 9 taps fully unrolled ----
    float C[2][2][4];                                        // [xh][nt][reg]
#pragma unroll
    for (int xh = 0; xh < 2; xh++)
#pragma unroll
        for (int nt = 0; nt < 2; nt++)
#pragma unroll
            for (int q = 0; q < 4; q++) C[xh][nt][q] = 0.0f;

    const uint32_t* pa = sm + t * PL + wid * RW + g;         // + dy*RW + dx + xh*16 (+8) (+4*PL)
    const uint2*    pb = (const uint2*)(sm + SMB_W) + g * 4 + t;   // word g*8 + 2t

#pragma unroll
    for (int tap = 0; tap < 9; tap++) {
        const int dy = tap / 3, dx = tap % 3;
        const uint2 b0 = pb[tap * 64];                       // nt = 0 (co 0..7)
        const uint2 b1 = pb[tap * 64 + 32];                  // nt = 1 (co 8..15)
        const int o = dy * RW + dx;                          // compile-time
#pragma unroll
        for (int xh = 0; xh < 2; xh++) {
            const int om = o + xh * 16;
            const uint32_t a0 = pa[om];                      // m=g,   k lo (plane t)
            const uint32_t a1 = pa[om + 8];                  // m=g+8, k lo
            const uint32_t a2 = pa[om + 4 * PL];             // m=g,   k hi (plane t+4)
            const uint32_t a3 = pa[om + 4 * PL + 8];         // m=g+8, k hi
            mma_f16(C[xh][0], a0, a1, a2, a3, b0.x, b0.y);
            mma_f16(C[xh][1], a0, a1, a2, a3, b1.x, b1.y);
        }
    }

    // ---- epilogue: c0->(xg,co), c1->(xg,co+1), c2->(xg+8,co), c3->(xg+8,co+1) ----
    float* ob = out + (size_t)b * 16 * 1024 * 1024;
    const int y = y0 + wid;
#pragma unroll
    for (int xh = 0; xh < 2; xh++) {
        const int xg = x0 + xh * 16 + g;
#pragma unroll
        for (int nt = 0; nt < 2; nt++) {
            const int co = nt * 8 + 2 * t;
            float* p0 = ob + ((size_t)co * 1024 + y) * 1024;
            float* p1 = p0 + 1024 * 1024;                    // co + 1
            p0[xg]     = C[xh][nt][0];
            p1[xg]     = C[xh][nt][1];
            p0[xg + 8] = C[xh][nt][2];
            p1[xg + 8] = C[xh][nt][3];
        }
    }
}

extern "C" void kernel_launch(void* const* d_in, const int* in_sizes, int n_in,
                              void* d_out, int out_size) {
    const float* x = (const float*)d_in[0];
    const float* w = (const float*)d_in[1];
    if (n_in >= 2 && in_sizes[0] == 16 * 16 * 9) {           // defensive order check
        const float* tp = x; x = w; w = tp;
    }
    float* out = (float*)d_out;

    cudaFuncSetAttribute(conv_mma_kernel,
                         cudaFuncAttributeMaxDynamicSharedMemorySize, SMEM_BYTES);
    dim3 grid(1024 / TWX, 1024 / TY, 8);
    conv_mma_kernel<<<grid, 512, SMEM_BYTES>>>(x, w, out);
}

// round 8
// speedup vs baseline: 9.9322x; 1.0943x over previous
#include <cuda_runtime.h>
#include <cstdint>

#define TWX  32
#define TY   16
#define SYY  18                  // TY + 2 halo rows
#define RW   34                  // row stride in pixels
#define PL   616                 // plane stride (words); 616 % 32 == 8 -> banks {0,8,16,24}+g
#define SMB_W (8 * PL)           // 4928 words
#define B_WORDS (9 * 128)        // 1152
#define SMEM_BYTES ((SMB_W + B_WORDS) * 4)   // 24320

static __device__ __forceinline__ uint32_t pack_h2(float lo, float hi) {
    uint32_t r;
    asm("cvt.rn.f16x2.f32 %0, %1, %2;" : "=r"(r) : "f"(hi), "f"(lo));  // 2nd src -> low half
    return r;
}

static __device__ __forceinline__ void mma_f16(float* c,
                                               uint32_t a0, uint32_t a1, uint32_t a2, uint32_t a3,
                                               uint32_t b0, uint32_t b1) {
    asm volatile(
        "mma.sync.aligned.m16n8k16.row.col.f32.f16.f16.f32 "
        "{%0,%1,%2,%3}, {%4,%5,%6,%7}, {%8,%9}, {%0,%1,%2,%3};"
        : "+f"(c[0]), "+f"(c[1]), "+f"(c[2]), "+f"(c[3])
        : "r"(a0), "r"(a1), "r"(a2), "r"(a3), "r"(b0), "r"(b1));
}

__global__ __launch_bounds__(256, 3)
void conv_mma_kernel(const float* __restrict__ x,
                     const float* __restrict__ wg,
                     float* __restrict__ out)
{
    extern __shared__ uint32_t sm[];
    const int tid = threadIdx.x, wid = tid >> 5, lane = tid & 31;
    const int g = lane >> 2, t = lane & 3;
    const int x0 = blockIdx.x * TWX;
    const int y0 = blockIdx.y * TY;
    const int b  = blockIdx.z;

    // ---- weights -> smem B (half2 pairs): word = tap*128 + co*8 + 2*(p&3) + (p>>2) ----
    if (tid < 128) {
        const int co = tid >> 3, p = tid & 7;
        const float* w0 = wg + (co * 16 + 2 * p) * 9;        // cin = 2p
        const float* w1 = w0 + 9;                            // cin = 2p+1
        const uint32_t sa = SMB_W + co * 8 + 2 * (p & 3) + (p >> 2);
#pragma unroll
        for (int tap = 0; tap < 9; tap++)
            sm[sa + tap * 128] = pack_h2(w0[tap], w1[tap]);  // low = cin 2p (k even)
    }

    // ---- input tile -> smem A: 8 cin-pair planes of packed half2; warp = plane ----
    {
        const int p = wid;                                   // 8 warps, 8 pair-planes
        const float* r0 = x + ((size_t)(b * 16 + 2 * p) * 1024 + (y0 - 1)) * 1024;
        const float* r1 = r0 + 1024 * 1024;                  // cin 2p+1
        const int gx_m = x0 - 1 + lane;
        const bool xok_m = (unsigned)gx_m < 1024u;
        const int gx_e = x0 + 31 + lane;
        const bool xok_e = (lane < 2) && ((unsigned)gx_e < 1024u);
        uint32_t sa = p * PL;
#pragma unroll
        for (int yy = 0; yy < SYY; yy++) {
            const int gy = y0 - 1 + yy;
            const bool yok = (unsigned)gy < 1024u;
            float v0 = 0.f, v1 = 0.f, e0 = 0.f, e1 = 0.f;
            if (yok && xok_m) { v0 = r0[gx_m]; v1 = r1[gx_m]; }
            if (yok && xok_e) { e0 = r0[gx_e]; e1 = r1[gx_e]; }
            sm[sa + lane] = pack_h2(v0, v1);
            if (lane < 2) sm[sa + 32 + lane] = pack_h2(e0, e1);
            r0 += 1024; r1 += 1024;
            sa += RW;
        }
    }
    __syncthreads();

    // ---- mainloop: warp owns rows yw, yw+1; A fragments cached per input row li ----
    float C[2][2][2][4];                                     // [r][xh][nt][q]
#pragma unroll
    for (int r = 0; r < 2; r++)
#pragma unroll
        for (int xh = 0; xh < 2; xh++)
#pragma unroll
            for (int nt = 0; nt < 2; nt++)
#pragma unroll
                for (int q = 0; q < 4; q++) C[r][xh][nt][q] = 0.0f;

    const int yw = 2 * wid;
    const uint32_t* pa = sm + t * PL + yw * RW + g;
    const uint2*    pb = (const uint2*)(sm + SMB_W) + g * 4 + t;   // word g*8 + 2t

#pragma unroll
    for (int li = 0; li < 4; li++) {                         // input row yw + li
        uint32_t av[2][3][2][2];                             // [xh][dx][kh][mh]
#pragma unroll
        for (int xh = 0; xh < 2; xh++)
#pragma unroll
            for (int dx = 0; dx < 3; dx++) {
                const int o = li * RW + xh * 16 + dx;        // compile-time constant
                av[xh][dx][0][0] = pa[o];                    // m=g,   k lo
                av[xh][dx][0][1] = pa[o + 8];                // m=g+8, k lo
                av[xh][dx][1][0] = pa[o + 4 * PL];           // m=g,   k hi
                av[xh][dx][1][1] = pa[o + 4 * PL + 8];       // m=g+8, k hi
            }
#pragma unroll
        for (int r = 0; r < 2; r++) {
            const int dy = li - r;
            if (dy >= 0 && dy <= 2) {
#pragma unroll
                for (int dx = 0; dx < 3; dx++) {
                    const int tap = dy * 3 + dx;
                    const uint2 b0 = pb[tap * 64];           // co 0..7
                    const uint2 b1 = pb[tap * 64 + 32];      // co 8..15
#pragma unroll
                    for (int xh = 0; xh < 2; xh++) {
                        mma_f16(C[r][xh][0],
                                av[xh][dx][0][0], av[xh][dx][0][1],
                                av[xh][dx][1][0], av[xh][dx][1][1],
                                b0.x, b0.y);
                        mma_f16(C[r][xh][1],
                                av[xh][dx][0][0], av[xh][dx][0][1],
                                av[xh][dx][1][0], av[xh][dx][1][1],
                                b1.x, b1.y);
                    }
                }
            }
        }
    }

    // ---- epilogue ----
    float* ob = out + (size_t)b * 16 * 1024 * 1024;
#pragma unroll
    for (int r = 0; r < 2; r++) {
        const int y = y0 + yw + r;
#pragma unroll
        for (int xh = 0; xh < 2; xh++) {
            const int xg = x0 + xh * 16 + g;
#pragma unroll
            for (int nt = 0; nt < 2; nt++) {
                const int co = nt * 8 + 2 * t;
                float* p0 = ob + ((size_t)co * 1024 + y) * 1024;
                float* p1 = p0 + 1024 * 1024;                // co + 1
                p0[xg]     = C[r][xh][nt][0];
                p1[xg]     = C[r][xh][nt][1];
                p0[xg + 8] = C[r][xh][nt][2];
                p1[xg + 8] = C[r][xh][nt][3];
            }
        }
    }
}

extern "C" void kernel_launch(void* const* d_in, const int* in_sizes, int n_in,
                              void* d_out, int out_size) {
    const float* x = (const float*)d_in[0];
    const float* w = (const float*)d_in[1];
    if (n_in >= 2 && in_sizes[0] == 16 * 16 * 9) {           // defensive order check
        const float* tp = x; x = w; w = tp;
    }
    float* out = (float*)d_out;

    cudaFuncSetAttribute(conv_mma_kernel,
                         cudaFuncAttributeMaxDynamicSharedMemorySize, SMEM_BYTES);
    dim3 grid(1024 / TWX, 1024 / TY, 8);
    conv_mma_kernel<<<grid, 256, SMEM_BYTES>>>(x, w, out);
}